// round 1
// baseline (speedup 1.0000x reference)
#include <cuda_runtime.h>

#define T  2048
#define E  1024
#define H  16
#define Dh 64
#define F  4096
#define EPS 1e-5f

// ---------------- scratch (static device globals; no allocation) ----------------
__device__ float g_Q[H * T * Dh];
__device__ float g_K[H * T * Dh];
__device__ float g_V[H * T * Dh];
__device__ float g_concat[T * E];
__device__ float g_attn[T * E];
__device__ float g_h[T * E];
__device__ float g_f[T * F];
__device__ float g_ffn[T * E];

// ---------------- generic 64x64 tile SGEMM (BK=16, 256 threads, 4x4 microtile) ----
// C[M,N] = A[M,K] @ B[K,N]  (+bias, +relu). All dims multiples of tile sizes here,
// so no bounds checks. m-tile = blockIdx.y, n-tile = blockIdx.x.
__device__ __forceinline__ void sgemm_tile(
    const float* __restrict__ A, const float* __restrict__ B,
    const float* __restrict__ bias, float* __restrict__ C,
    int N, int K, bool relu)
{
    __shared__ float As[16 * 64];   // As[k][m]
    __shared__ float Bs[16 * 64];   // Bs[k][n]

    const int tid = threadIdx.x;          // 0..255
    const int tx  = tid & 15;             // n sub-tile
    const int ty  = tid >> 4;             // m sub-tile
    const int m0  = blockIdx.y * 64;
    const int n0  = blockIdx.x * 64;

    const int arow = tid >> 2;            // 0..63
    const int acol = (tid & 3) << 2;      // 0,4,8,12
    const int brow = tid >> 4;            // 0..15
    const int bcol = (tid & 15) << 2;     // 0..60

    float acc[4][4] = {};

    for (int k0 = 0; k0 < K; k0 += 16) {
        float4 av = *reinterpret_cast<const float4*>(A + (size_t)(m0 + arow) * K + k0 + acol);
        float4 bv = *reinterpret_cast<const float4*>(B + (size_t)(k0 + brow) * N + n0 + bcol);
        As[(acol + 0) * 64 + arow] = av.x;
        As[(acol + 1) * 64 + arow] = av.y;
        As[(acol + 2) * 64 + arow] = av.z;
        As[(acol + 3) * 64 + arow] = av.w;
        *reinterpret_cast<float4*>(Bs + brow * 64 + bcol) = bv;
        __syncthreads();
        #pragma unroll
        for (int kk = 0; kk < 16; ++kk) {
            float a[4], b[4];
            #pragma unroll
            for (int i = 0; i < 4; ++i) a[i] = As[kk * 64 + ty * 4 + i];
            #pragma unroll
            for (int j = 0; j < 4; ++j) b[j] = Bs[kk * 64 + tx * 4 + j];
            #pragma unroll
            for (int i = 0; i < 4; ++i)
                #pragma unroll
                for (int j = 0; j < 4; ++j)
                    acc[i][j] += a[i] * b[j];
        }
        __syncthreads();
    }

    #pragma unroll
    for (int i = 0; i < 4; ++i) {
        const int m = m0 + ty * 4 + i;
        #pragma unroll
        for (int j = 0; j < 4; ++j) {
            const int n = n0 + tx * 4 + j;
            float c = acc[i][j];
            if (bias) c += bias[n];
            if (relu) c = fmaxf(c, 0.0f);
            C[(size_t)m * N + n] = c;
        }
    }
}

// ---------------- QKV projections: 48 batched GEMMs [2048,1024]x[1024,64] ----------
__global__ void qkv_kernel(const float* __restrict__ x,
                           const float* __restrict__ wq,
                           const float* __restrict__ wk,
                           const float* __restrict__ wv)
{
    const int z = blockIdx.z;             // 0..47
    const int which = z >> 4;             // 0=q,1=k,2=v
    const int h = z & 15;
    const float* B = (which == 0 ? wq : which == 1 ? wk : wv) + (size_t)h * E * Dh;
    float* C       = (which == 0 ? g_Q : which == 1 ? g_K : g_V) + (size_t)h * T * Dh;
    sgemm_tile(x, B, nullptr, C, Dh, E, false);
}

__global__ void pool_kernel(const float* __restrict__ pool_w)
{
    sgemm_tile(g_concat, pool_w, nullptr, g_attn, E, E, false);
}

__global__ void ffn1_kernel(const float* __restrict__ w, const float* __restrict__ b)
{
    sgemm_tile(g_h, w, b, g_f, F, E, true);
}

__global__ void ffn2_kernel(const float* __restrict__ w, const float* __restrict__ b)
{
    sgemm_tile(g_f, w, b, g_ffn, E, F, false);
}

// ---------------- causal attention: one warp per query row, online softmax --------
// grid: (T/8, H), block: 256 (8 warps). Writes directly into concat layout.
__global__ void attn_kernel()
{
    __shared__ float q_sh[8][64];
    __shared__ float p_sh[8][32];

    const int h    = blockIdx.y;
    const int w    = threadIdx.x >> 5;
    const int lane = threadIdx.x & 31;
    const int qrow = blockIdx.x * 8 + w;

    const float* Qh = g_Q + (size_t)h * T * Dh;
    const float* Kh = g_K + (size_t)h * T * Dh;
    const float* Vh = g_V + (size_t)h * T * Dh;

    q_sh[w][lane]      = Qh[qrow * Dh + lane];
    q_sh[w][lane + 32] = Qh[qrow * Dh + lane + 32];
    __syncwarp();

    float m = -1e30f, l = 0.0f, o0 = 0.0f, o1 = 0.0f;

    for (int kb = 0; kb <= qrow; kb += 32) {
        const int j = kb + lane;
        float s = -1e30f;
        if (j <= qrow) {
            const float* kr = Kh + j * Dh;
            float acc = 0.0f;
            #pragma unroll
            for (int d = 0; d < 64; ++d) acc += q_sh[w][d] * kr[d];
            s = acc * 0.125f;                       // 1/sqrt(64)
        }
        // chunk max
        float mc = s;
        #pragma unroll
        for (int o = 16; o; o >>= 1) mc = fmaxf(mc, __shfl_xor_sync(0xffffffffu, mc, o));
        const float mnew = fmaxf(m, mc);
        const float p = (j <= qrow) ? __expf(s - mnew) : 0.0f;
        float ps = p;
        #pragma unroll
        for (int o = 16; o; o >>= 1) ps += __shfl_xor_sync(0xffffffffu, ps, o);
        const float alpha = __expf(m - mnew);       // m=-1e30 first iter -> 0
        l = l * alpha + ps;
        o0 *= alpha; o1 *= alpha;

        p_sh[w][lane] = p;
        __syncwarp();
        const int nk = min(32, qrow - kb + 1);
        const float* vb = Vh + kb * Dh;
        for (int jj = 0; jj < nk; ++jj) {
            const float pj = p_sh[w][jj];
            o0 += pj * vb[jj * Dh + lane];
            o1 += pj * vb[jj * Dh + lane + 32];
        }
        __syncwarp();
        m = mnew;
    }

    const float inv = 1.0f / l;
    g_concat[(size_t)qrow * E + h * Dh + lane]      = o0 * inv;
    g_concat[(size_t)qrow * E + h * Dh + lane + 32] = o1 * inv;
}

// ---------------- residual + LayerNorm: one block (256 thr) per row ---------------
__device__ __forceinline__ void ln_body(const float* __restrict__ a,
                                        const float* __restrict__ b,
                                        const float* __restrict__ gamma,
                                        const float* __restrict__ beta,
                                        float* __restrict__ out)
{
    const int row = blockIdx.x;
    const int tid = threadIdx.x;

    float v[4];
    float s = 0.0f, s2 = 0.0f;
    #pragma unroll
    for (int i = 0; i < 4; ++i) {
        const int e = tid + i * 256;
        const float val = a[(size_t)row * E + e] + b[(size_t)row * E + e];
        v[i] = val;
        s += val;
        s2 += val * val;
    }

    __shared__ float shs[32], shq[32];
    #pragma unroll
    for (int o = 16; o; o >>= 1) {
        s  += __shfl_xor_sync(0xffffffffu, s, o);
        s2 += __shfl_xor_sync(0xffffffffu, s2, o);
    }
    const int warp = tid >> 5, lane = tid & 31;
    if (lane == 0) { shs[warp] = s; shq[warp] = s2; }
    __syncthreads();
    if (tid < 32) {
        s  = (tid < 8) ? shs[tid] : 0.0f;
        s2 = (tid < 8) ? shq[tid] : 0.0f;
        #pragma unroll
        for (int o = 4; o; o >>= 1) {
            s  += __shfl_xor_sync(0xffffffffu, s, o);
            s2 += __shfl_xor_sync(0xffffffffu, s2, o);
        }
        if (tid == 0) { shs[0] = s; shq[0] = s2; }
    }
    __syncthreads();
    s = shs[0]; s2 = shq[0];

    const float mean = s * (1.0f / E);
    const float var  = s2 * (1.0f / E) - mean * mean;
    const float inv  = rsqrtf(var + EPS);
    const float g    = gamma[0];
    #pragma unroll
    for (int i = 0; i < 4; ++i) {
        const int e = tid + i * 256;
        out[(size_t)row * E + e] = g * (v[i] - mean) * inv + beta[e];
    }
}

__global__ void ln1_kernel(const float* __restrict__ x,
                           const float* __restrict__ gamma,
                           const float* __restrict__ beta)
{
    ln_body(x, g_attn, gamma, beta, g_h);
}

__global__ void ln2_kernel(const float* __restrict__ gamma,
                           const float* __restrict__ beta,
                           float* __restrict__ out)
{
    ln_body(g_h, g_ffn, gamma, beta, out);
}

// ---------------- launch -----------------------------------------------------------
extern "C" void kernel_launch(void* const* d_in, const int* in_sizes, int n_in,
                              void* d_out, int out_size)
{
    const float* x      = (const float*)d_in[0];
    const float* wq     = (const float*)d_in[1];
    const float* wk     = (const float*)d_in[2];
    const float* wv     = (const float*)d_in[3];
    const float* pool_w = (const float*)d_in[4];
    const float* l1_w   = (const float*)d_in[5];
    const float* l1_b   = (const float*)d_in[6];
    const float* l2_w   = (const float*)d_in[7];
    const float* l2_b   = (const float*)d_in[8];
    const float* gamma  = (const float*)d_in[9];
    const float* beta   = (const float*)d_in[10];
    float* out = (float*)d_out;

    qkv_kernel<<<dim3(1, T / 64, 48), 256>>>(x, wq, wk, wv);
    attn_kernel<<<dim3(T / 8, H), 256>>>();
    pool_kernel<<<dim3(E / 64, T / 64), 256>>>(pool_w);
    ln1_kernel<<<T, 256>>>(x, gamma, beta);
    ffn1_kernel<<<dim3(F / 64, T / 64), 256>>>(l1_w, l1_b);
    ffn2_kernel<<<dim3(E / 64, T / 64), 256>>>(l2_w, l2_b);
    ln2_kernel<<<T, 256>>>(gamma, beta, out);
}

// round 2
// speedup vs baseline: 5.5508x; 5.5508x over previous
#include <cuda_runtime.h>

#define T  2048
#define E  1024
#define H  16
#define Dh 64
#define F  4096
#define EPS 1e-5f

// ---------------- scratch (static device globals; no allocation) ----------------
__device__ float g_Q[H * T * Dh];
__device__ float g_K[H * T * Dh];
__device__ float g_V[H * T * Dh];
__device__ float g_concat[T * E];
__device__ float g_attn[T * E];
__device__ float g_h[T * E];
__device__ float g_f[T * F];
__device__ float g_ffn[T * E];

// =====================================================================
// Generic 128x128 SGEMM, BK=16, 256 threads, 8x8 microtile, double-buffered
// C[M,N] = A[M,K] @ B[K,N] (+bias)(+relu)
// =====================================================================
template<int BIAS, int RELU>
__global__ void __launch_bounds__(256) gemm128(
    const float* __restrict__ A, const float* __restrict__ B,
    const float* __restrict__ bias, float* __restrict__ C,
    int M, int N, int K)
{
    __shared__ float As[2][16][132];   // [k][m], padded stride
    __shared__ float Bs[2][16][128];   // [k][n]

    const int tid = threadIdx.x;
    const int tx  = tid & 15;          // n micro
    const int ty  = tid >> 4;          // m micro
    const int m0  = blockIdx.y * 128;
    const int n0  = blockIdx.x * 128;

    const int arow = tid >> 2;         // 0..63  (and +64)
    const int acol = (tid & 3) << 2;   // 0,4,8,12
    const int brow = tid >> 5;         // 0..7   (and +8)
    const int bcol = (tid & 31) << 2;  // 0..124

    const float* aptr0 = A + (size_t)(m0 + arow) * K + acol;
    const float* aptr1 = A + (size_t)(m0 + arow + 64) * K + acol;
    const float* bptr0 = B + (size_t)brow * N + n0 + bcol;
    const float* bptr1 = B + (size_t)(brow + 8) * N + n0 + bcol;

    float acc[8][8] = {};
    float4 la0, la1, lb0, lb1;

    const int KT = K >> 4;

    // preload tile 0
    la0 = *reinterpret_cast<const float4*>(aptr0);
    la1 = *reinterpret_cast<const float4*>(aptr1);
    lb0 = *reinterpret_cast<const float4*>(bptr0);
    lb1 = *reinterpret_cast<const float4*>(bptr1);

    int buf = 0;
    {
        As[0][acol + 0][arow]      = la0.x;
        As[0][acol + 1][arow]      = la0.y;
        As[0][acol + 2][arow]      = la0.z;
        As[0][acol + 3][arow]      = la0.w;
        As[0][acol + 0][arow + 64] = la1.x;
        As[0][acol + 1][arow + 64] = la1.y;
        As[0][acol + 2][arow + 64] = la1.z;
        As[0][acol + 3][arow + 64] = la1.w;
        *reinterpret_cast<float4*>(&Bs[0][brow][bcol])     = lb0;
        *reinterpret_cast<float4*>(&Bs[0][brow + 8][bcol]) = lb1;
    }
    __syncthreads();

    for (int kt = 0; kt < KT; ++kt) {
        if (kt + 1 < KT) {
            const int ko = (kt + 1) << 4;
            la0 = *reinterpret_cast<const float4*>(aptr0 + ko);
            la1 = *reinterpret_cast<const float4*>(aptr1 + ko);
            lb0 = *reinterpret_cast<const float4*>(bptr0 + (size_t)ko * N);
            lb1 = *reinterpret_cast<const float4*>(bptr1 + (size_t)ko * N);
        }
        #pragma unroll
        for (int kk = 0; kk < 16; ++kk) {
            float4 a0 = *reinterpret_cast<const float4*>(&As[buf][kk][ty * 8]);
            float4 a1 = *reinterpret_cast<const float4*>(&As[buf][kk][ty * 8 + 4]);
            float4 b0 = *reinterpret_cast<const float4*>(&Bs[buf][kk][tx * 8]);
            float4 b1 = *reinterpret_cast<const float4*>(&Bs[buf][kk][tx * 8 + 4]);
            float a[8] = {a0.x, a0.y, a0.z, a0.w, a1.x, a1.y, a1.z, a1.w};
            float b[8] = {b0.x, b0.y, b0.z, b0.w, b1.x, b1.y, b1.z, b1.w};
            #pragma unroll
            for (int i = 0; i < 8; ++i)
                #pragma unroll
                for (int j = 0; j < 8; ++j)
                    acc[i][j] += a[i] * b[j];
        }
        if (kt + 1 < KT) {
            const int nb = buf ^ 1;
            As[nb][acol + 0][arow]      = la0.x;
            As[nb][acol + 1][arow]      = la0.y;
            As[nb][acol + 2][arow]      = la0.z;
            As[nb][acol + 3][arow]      = la0.w;
            As[nb][acol + 0][arow + 64] = la1.x;
            As[nb][acol + 1][arow + 64] = la1.y;
            As[nb][acol + 2][arow + 64] = la1.z;
            As[nb][acol + 3][arow + 64] = la1.w;
            *reinterpret_cast<float4*>(&Bs[nb][brow][bcol])     = lb0;
            *reinterpret_cast<float4*>(&Bs[nb][brow + 8][bcol]) = lb1;
            __syncthreads();
            buf = nb;
        }
    }

    #pragma unroll
    for (int i = 0; i < 8; ++i) {
        const int m = m0 + ty * 8 + i;
        #pragma unroll
        for (int j = 0; j < 8; ++j) {
            const int n = n0 + tx * 8 + j;
            float c = acc[i][j];
            if (BIAS) c += bias[n];
            if (RELU) c = fmaxf(c, 0.0f);
            C[(size_t)m * N + n] = c;
        }
    }
}

// =====================================================================
// Fused QKV GEMM: X[2048,1024] @ Wqkv[1024,3072] where columns are
// (which, head, d) drawn from wq/wk/wv[h][e][d]. Same tiling as gemm128.
// =====================================================================
__global__ void __launch_bounds__(256) qkv_gemm(
    const float* __restrict__ A,
    const float* __restrict__ wq, const float* __restrict__ wk,
    const float* __restrict__ wv)
{
    __shared__ float As[2][16][132];
    __shared__ float Bs[2][16][128];

    const int tid = threadIdx.x;
    const int tx  = tid & 15;
    const int ty  = tid >> 4;
    const int m0  = blockIdx.y * 128;
    const int n0  = blockIdx.x * 128;

    const int arow = tid >> 2;
    const int acol = (tid & 3) << 2;
    const int brow = tid >> 5;
    const int bcol = (tid & 31) << 2;

    const int K = E;

    const float* aptr0 = A + (size_t)(m0 + arow) * K + acol;
    const float* aptr1 = A + (size_t)(m0 + arow + 64) * K + acol;

    // per-thread fixed column of the virtual Wqkv matrix
    const int n      = n0 + bcol;
    const int which  = n >> 10;
    const int head   = (n >> 6) & 15;
    const int d      = n & 63;
    const float* wsel = (which == 0 ? wq : which == 1 ? wk : wv);
    const float* bbase = wsel + ((size_t)head * E) * Dh + d;   // + e*Dh per k-row

    float acc[8][8] = {};
    float4 la0, la1, lb0, lb1;
    const int KT = K >> 4;

    la0 = *reinterpret_cast<const float4*>(aptr0);
    la1 = *reinterpret_cast<const float4*>(aptr1);
    lb0 = *reinterpret_cast<const float4*>(bbase + (size_t)brow * Dh);
    lb1 = *reinterpret_cast<const float4*>(bbase + (size_t)(brow + 8) * Dh);

    int buf = 0;
    As[0][acol + 0][arow]      = la0.x;
    As[0][acol + 1][arow]      = la0.y;
    As[0][acol + 2][arow]      = la0.z;
    As[0][acol + 3][arow]      = la0.w;
    As[0][acol + 0][arow + 64] = la1.x;
    As[0][acol + 1][arow + 64] = la1.y;
    As[0][acol + 2][arow + 64] = la1.z;
    As[0][acol + 3][arow + 64] = la1.w;
    *reinterpret_cast<float4*>(&Bs[0][brow][bcol])     = lb0;
    *reinterpret_cast<float4*>(&Bs[0][brow + 8][bcol]) = lb1;
    __syncthreads();

    for (int kt = 0; kt < KT; ++kt) {
        if (kt + 1 < KT) {
            const int ko = (kt + 1) << 4;
            la0 = *reinterpret_cast<const float4*>(aptr0 + ko);
            la1 = *reinterpret_cast<const float4*>(aptr1 + ko);
            lb0 = *reinterpret_cast<const float4*>(bbase + (size_t)(ko + brow) * Dh);
            lb1 = *reinterpret_cast<const float4*>(bbase + (size_t)(ko + brow + 8) * Dh);
        }
        #pragma unroll
        for (int kk = 0; kk < 16; ++kk) {
            float4 a0 = *reinterpret_cast<const float4*>(&As[buf][kk][ty * 8]);
            float4 a1 = *reinterpret_cast<const float4*>(&As[buf][kk][ty * 8 + 4]);
            float4 b0 = *reinterpret_cast<const float4*>(&Bs[buf][kk][tx * 8]);
            float4 b1 = *reinterpret_cast<const float4*>(&Bs[buf][kk][tx * 8 + 4]);
            float a[8] = {a0.x, a0.y, a0.z, a0.w, a1.x, a1.y, a1.z, a1.w};
            float b[8] = {b0.x, b0.y, b0.z, b0.w, b1.x, b1.y, b1.z, b1.w};
            #pragma unroll
            for (int i = 0; i < 8; ++i)
                #pragma unroll
                for (int j = 0; j < 8; ++j)
                    acc[i][j] += a[i] * b[j];
        }
        if (kt + 1 < KT) {
            const int nb = buf ^ 1;
            As[nb][acol + 0][arow]      = la0.x;
            As[nb][acol + 1][arow]      = la0.y;
            As[nb][acol + 2][arow]      = la0.z;
            As[nb][acol + 3][arow]      = la0.w;
            As[nb][acol + 0][arow + 64] = la1.x;
            As[nb][acol + 1][arow + 64] = la1.y;
            As[nb][acol + 2][arow + 64] = la1.z;
            As[nb][acol + 3][arow + 64] = la1.w;
            *reinterpret_cast<float4*>(&Bs[nb][brow][bcol])     = lb0;
            *reinterpret_cast<float4*>(&Bs[nb][brow + 8][bcol]) = lb1;
            __syncthreads();
            buf = nb;
        }
    }

    #pragma unroll
    for (int i = 0; i < 8; ++i) {
        const int m = m0 + ty * 8 + i;
        #pragma unroll
        for (int j = 0; j < 8; ++j) {
            const int nn = n0 + tx * 8 + j;
            const int wsel2 = nn >> 10;
            const int h2    = (nn >> 6) & 15;
            const int d2    = nn & 63;
            float* dst = (wsel2 == 0 ? g_Q : wsel2 == 1 ? g_K : g_V);
            dst[((size_t)h2 * T + m) * Dh + d2] = acc[i][j];
        }
    }
}

// =====================================================================
// Tiled causal attention: block = 256 thr (8 warps), 32 q-rows per block,
// K/V tiles (32x64) staged in smem. Each warp owns 4 q-rows.
// =====================================================================
__global__ void __launch_bounds__(256) attn_kernel()
{
    __shared__ float4 Q4[32][17];   // 32 rows x 68 floats (pad 4)
    __shared__ float4 K4[32][17];
    __shared__ float4 V4[32][17];
    __shared__ float  p_sh[8][4][32];

    const int tid  = threadIdx.x;
    const int w    = tid >> 5;
    const int lane = tid & 31;
    const int base = blockIdx.x * 32;
    const int h    = blockIdx.y;

    const float* Qh = g_Q + (size_t)h * T * Dh;
    const float* Kh = g_K + (size_t)h * T * Dh;
    const float* Vh = g_V + (size_t)h * T * Dh;
    const float* Vf = (const float*)V4;    // row stride 68 floats

    // load Q tile (32x64): 512 float4s, 2 per thread
    #pragma unroll
    for (int i = 0; i < 2; ++i) {
        const int idx = tid + i * 256;
        const int row = idx >> 4, c4 = idx & 15;
        Q4[row][c4] = *reinterpret_cast<const float4*>(Qh + (size_t)(base + row) * Dh + c4 * 4);
    }

    float m[4] = {-1e30f, -1e30f, -1e30f, -1e30f};
    float l[4] = {};
    float o0[4] = {}, o1[4] = {};

    for (int kb = 0; kb <= base; kb += 32) {
        __syncthreads();
        #pragma unroll
        for (int i = 0; i < 2; ++i) {
            const int idx = tid + i * 256;
            const int row = idx >> 4, c4 = idx & 15;
            K4[row][c4] = *reinterpret_cast<const float4*>(Kh + (size_t)(kb + row) * Dh + c4 * 4);
            V4[row][c4] = *reinterpret_cast<const float4*>(Vh + (size_t)(kb + row) * Dh + c4 * 4);
        }
        __syncthreads();

        // ---- QK^T for this warp's 4 rows, this lane's column j = kb+lane
        float s0 = 0.f, s1 = 0.f, s2 = 0.f, s3 = 0.f;
        #pragma unroll
        for (int d4 = 0; d4 < 16; ++d4) {
            const float4 kv = K4[lane][d4];
            float4 q;
            q = Q4[w * 4 + 0][d4]; s0 += q.x*kv.x + q.y*kv.y + q.z*kv.z + q.w*kv.w;
            q = Q4[w * 4 + 1][d4]; s1 += q.x*kv.x + q.y*kv.y + q.z*kv.z + q.w*kv.w;
            q = Q4[w * 4 + 2][d4]; s2 += q.x*kv.x + q.y*kv.y + q.z*kv.z + q.w*kv.w;
            q = Q4[w * 4 + 3][d4]; s3 += q.x*kv.x + q.y*kv.y + q.z*kv.z + q.w*kv.w;
        }
        float sv[4] = {s0, s1, s2, s3};
        const int j = kb + lane;

        #pragma unroll
        for (int r = 0; r < 4; ++r) {
            const int qrow = base + w * 4 + r;
            const bool act = (j <= qrow);
            float s = act ? sv[r] * 0.125f : -1e30f;
            float mc = s;
            #pragma unroll
            for (int o = 16; o; o >>= 1) mc = fmaxf(mc, __shfl_xor_sync(0xffffffffu, mc, o));
            const float mnew = fmaxf(m[r], mc);
            const float p = act ? __expf(s - mnew) : 0.0f;
            float ps = p;
            #pragma unroll
            for (int o = 16; o; o >>= 1) ps += __shfl_xor_sync(0xffffffffu, ps, o);
            const float alpha = __expf(m[r] - mnew);
            l[r]  = l[r] * alpha + ps;
            o0[r] *= alpha;
            o1[r] *= alpha;
            m[r]  = mnew;
            p_sh[w][r][lane] = p;
        }
        __syncwarp();

        // ---- P @ V (each lane owns dims lane, lane+32)
        #pragma unroll 4
        for (int jj = 0; jj < 32; ++jj) {
            const float va = Vf[jj * 68 + lane];
            const float vb = Vf[jj * 68 + lane + 32];
            const float pa = p_sh[w][0][jj];
            const float pb = p_sh[w][1][jj];
            const float pc = p_sh[w][2][jj];
            const float pd = p_sh[w][3][jj];
            o0[0] += pa * va;  o1[0] += pa * vb;
            o0[1] += pb * va;  o1[1] += pb * vb;
            o0[2] += pc * va;  o1[2] += pc * vb;
            o0[3] += pd * va;  o1[3] += pd * vb;
        }
        __syncwarp();
    }

    #pragma unroll
    for (int r = 0; r < 4; ++r) {
        const int qrow = base + w * 4 + r;
        const float inv = 1.0f / l[r];
        g_concat[(size_t)qrow * E + h * Dh + lane]      = o0[r] * inv;
        g_concat[(size_t)qrow * E + h * Dh + lane + 32] = o1[r] * inv;
    }
}

// ---------------- residual + LayerNorm ----------------
__device__ __forceinline__ void ln_body(const float* __restrict__ a,
                                        const float* __restrict__ b,
                                        const float* __restrict__ gamma,
                                        const float* __restrict__ beta,
                                        float* __restrict__ out)
{
    const int row = blockIdx.x;
    const int tid = threadIdx.x;

    float v[4];
    float s = 0.0f, s2 = 0.0f;
    #pragma unroll
    for (int i = 0; i < 4; ++i) {
        const int e = tid + i * 256;
        const float val = a[(size_t)row * E + e] + b[(size_t)row * E + e];
        v[i] = val;
        s += val;
        s2 += val * val;
    }

    __shared__ float shs[32], shq[32];
    #pragma unroll
    for (int o = 16; o; o >>= 1) {
        s  += __shfl_xor_sync(0xffffffffu, s, o);
        s2 += __shfl_xor_sync(0xffffffffu, s2, o);
    }
    const int warp = tid >> 5, lane = tid & 31;
    if (lane == 0) { shs[warp] = s; shq[warp] = s2; }
    __syncthreads();
    if (tid < 32) {
        s  = (tid < 8) ? shs[tid] : 0.0f;
        s2 = (tid < 8) ? shq[tid] : 0.0f;
        #pragma unroll
        for (int o = 4; o; o >>= 1) {
            s  += __shfl_xor_sync(0xffffffffu, s, o);
            s2 += __shfl_xor_sync(0xffffffffu, s2, o);
        }
        if (tid == 0) { shs[0] = s; shq[0] = s2; }
    }
    __syncthreads();
    s = shs[0]; s2 = shq[0];

    const float mean = s * (1.0f / E);
    const float var  = s2 * (1.0f / E) - mean * mean;
    const float inv  = rsqrtf(var + EPS);
    const float g    = gamma[0];
    #pragma unroll
    for (int i = 0; i < 4; ++i) {
        const int e = tid + i * 256;
        out[(size_t)row * E + e] = g * (v[i] - mean) * inv + beta[e];
    }
}

__global__ void ln1_kernel(const float* __restrict__ x,
                           const float* __restrict__ gamma,
                           const float* __restrict__ beta)
{
    ln_body(x, g_attn, gamma, beta, g_h);
}

__global__ void ln2_kernel(const float* __restrict__ gamma,
                           const float* __restrict__ beta,
                           float* __restrict__ out)
{
    ln_body(g_h, g_ffn, gamma, beta, out);
}

// ---------------- launch ----------------
extern "C" void kernel_launch(void* const* d_in, const int* in_sizes, int n_in,
                              void* d_out, int out_size)
{
    const float* x      = (const float*)d_in[0];
    const float* wq     = (const float*)d_in[1];
    const float* wk     = (const float*)d_in[2];
    const float* wv     = (const float*)d_in[3];
    const float* pool_w = (const float*)d_in[4];
    const float* l1_w   = (const float*)d_in[5];
    const float* l1_b   = (const float*)d_in[6];
    const float* l2_w   = (const float*)d_in[7];
    const float* l2_b   = (const float*)d_in[8];
    const float* gamma  = (const float*)d_in[9];
    const float* beta   = (const float*)d_in[10];
    float* out = (float*)d_out;

    float* pQ; cudaGetSymbolAddress((void**)&pQ, g_Q);
    float* pC; cudaGetSymbolAddress((void**)&pC, g_concat);
    float* pA; cudaGetSymbolAddress((void**)&pA, g_attn);
    float* pH; cudaGetSymbolAddress((void**)&pH, g_h);
    float* pF; cudaGetSymbolAddress((void**)&pF, g_f);
    float* pN; cudaGetSymbolAddress((void**)&pN, g_ffn);

    qkv_gemm<<<dim3(3072 / 128, T / 128), 256>>>(x, wq, wk, wv);
    attn_kernel<<<dim3(T / 32, H), 256>>>();
    gemm128<0, 0><<<dim3(E / 128, T / 128), 256>>>(pC, pool_w, nullptr, pA, T, E, E);
    ln1_kernel<<<T, 256>>>(x, gamma, beta);
    gemm128<1, 1><<<dim3(F / 128, T / 128), 256>>>(pH, l1_w, l1_b, pF, T, F, E);
    gemm128<1, 0><<<dim3(E / 128, T / 128), 256>>>(pF, l2_w, l2_b, pN, T, E, F);
    ln2_kernel<<<T, 256>>>(gamma, beta, out);
}

// round 3
// speedup vs baseline: 9.2625x; 1.6687x over previous
#include <cuda_runtime.h>
#include <cuda_bf16.h>
#include <cstdint>

#define T  2048
#define E  1024
#define H  16
#define Dh 64
#define F  4096
#define EPS 1e-5f

// ---------------- scratch ----------------
__device__ float g_Q[H * T * Dh];
__device__ float g_K[H * T * Dh];
__device__ float g_V[H * T * Dh];
__device__ float g_concat[T * E];
__device__ float g_attn[T * E];
__device__ float g_h[T * E];
__device__ float g_f[T * F];
__device__ float g_ffn[T * E];

// ---------------- mma helpers ----------------
__device__ __forceinline__ uint32_t smem_u32(const void* p) {
    return (uint32_t)__cvta_generic_to_shared(p);
}
__device__ __forceinline__ void ldm_x4(uint32_t& r0, uint32_t& r1, uint32_t& r2, uint32_t& r3, uint32_t a) {
    asm volatile("ldmatrix.sync.aligned.m8n8.x4.shared.b16 {%0,%1,%2,%3},[%4];"
                 : "=r"(r0), "=r"(r1), "=r"(r2), "=r"(r3) : "r"(a));
}
__device__ __forceinline__ void ldm_x2t(uint32_t& r0, uint32_t& r1, uint32_t a) {
    asm volatile("ldmatrix.sync.aligned.m8n8.x2.trans.shared.b16 {%0,%1},[%2];"
                 : "=r"(r0), "=r"(r1) : "r"(a));
}
__device__ __forceinline__ void mma16816(float* d, const uint32_t* a, const uint32_t* b) {
    asm volatile(
        "mma.sync.aligned.m16n8k16.row.col.f32.bf16.bf16.f32 "
        "{%0,%1,%2,%3},{%4,%5,%6,%7},{%8,%9},{%0,%1,%2,%3};"
        : "+f"(d[0]), "+f"(d[1]), "+f"(d[2]), "+f"(d[3])
        : "r"(a[0]), "r"(a[1]), "r"(a[2]), "r"(a[3]), "r"(b[0]), "r"(b[1]));
}
__device__ __forceinline__ uint32_t pack_b2(__nv_bfloat16 a, __nv_bfloat16 b) {
    __nv_bfloat162 t = __halves2bfloat162(a, b);
    return *reinterpret_cast<uint32_t*>(&t);
}
// split float4 -> bf16 hi (uint2) + bf16 lo (uint2)
__device__ __forceinline__ void split4(float4 v, uint2& hi, uint2& lo) {
    float f[4] = {v.x, v.y, v.z, v.w};
    __nv_bfloat16 h[4], l[4];
    #pragma unroll
    for (int i = 0; i < 4; ++i) {
        h[i] = __float2bfloat16(f[i]);
        l[i] = __float2bfloat16(f[i] - __bfloat162float(h[i]));
    }
    hi.x = pack_b2(h[0], h[1]); hi.y = pack_b2(h[2], h[3]);
    lo.x = pack_b2(l[0], l[1]); lo.y = pack_b2(l[2], l[3]);
}

// =====================================================================
// bf16x3 tensor-core GEMM: 128x128 tile, BK=32, 256 thr (8 warps = 2m x 4n)
// C = A[M,K] @ B[K,N] in ~fp32 accuracy via 3-term bf16 split.
// =====================================================================
template<int BIAS, int RELU>
__global__ void __launch_bounds__(256) gemm_bf16(
    const float* __restrict__ A, const float* __restrict__ B,
    const float* __restrict__ bias, float* __restrict__ C,
    int N, int K)
{
    __shared__ __align__(16) __nv_bfloat16 Ahi[2][128][24];
    __shared__ __align__(16) __nv_bfloat16 Alo[2][128][24];
    __shared__ __align__(16) __nv_bfloat16 Bhi[2][16][136];
    __shared__ __align__(16) __nv_bfloat16 Blo[2][16][136];

    const int tid  = threadIdx.x;
    const int lane = tid & 31;
    const int wid  = tid >> 5;
    const int wm   = wid >> 2;           // 0..1 -> m offset 64*wm
    const int wn   = wid & 3;            // 0..3 -> n offset 32*wn
    const int m0   = blockIdx.y * 128;
    const int n0   = blockIdx.x * 128;

    const int KT = K >> 5;               // BK = 32

    float4 a_reg[4], b_reg[4];

    auto load_tile = [&](int kt) {
        const int k0 = kt << 5;
        #pragma unroll
        for (int i = 0; i < 4; ++i) {
            const int idx = tid + i * 256;
            const int row = idx >> 3, c4 = idx & 7;      // A: [128][8 float4]
            a_reg[i] = *reinterpret_cast<const float4*>(A + (size_t)(m0 + row) * K + k0 + c4 * 4);
        }
        #pragma unroll
        for (int i = 0; i < 4; ++i) {
            const int idx = tid + i * 256;
            const int row = idx >> 5, c4 = idx & 31;     // B: [32][32 float4]
            b_reg[i] = *reinterpret_cast<const float4*>(B + (size_t)(k0 + row) * N + n0 + c4 * 4);
        }
    };
    auto store_tile = [&]() {
        #pragma unroll
        for (int i = 0; i < 4; ++i) {
            const int idx = tid + i * 256;
            const int row = idx >> 3, c4 = idx & 7;
            const int slab = c4 >> 2, kk = (c4 & 3) * 4;
            uint2 hi, lo; split4(a_reg[i], hi, lo);
            *reinterpret_cast<uint2*>(&Ahi[slab][row][kk]) = hi;
            *reinterpret_cast<uint2*>(&Alo[slab][row][kk]) = lo;
        }
        #pragma unroll
        for (int i = 0; i < 4; ++i) {
            const int idx = tid + i * 256;
            const int row = idx >> 5, c4 = idx & 31;
            const int slab = row >> 4, kk = row & 15;
            uint2 hi, lo; split4(b_reg[i], hi, lo);
            *reinterpret_cast<uint2*>(&Bhi[slab][kk][c4 * 4]) = hi;
            *reinterpret_cast<uint2*>(&Blo[slab][kk][c4 * 4]) = lo;
        }
    };

    float acc[4][4][4] = {};

    load_tile(0);
    store_tile();
    __syncthreads();

    const int a_row = (lane & 15);
    const int a_col = (lane >> 4) * 8;

    for (int kt = 0; kt < KT; ++kt) {
        if (kt + 1 < KT) load_tile(kt + 1);

        #pragma unroll
        for (int slab = 0; slab < 2; ++slab) {
            uint32_t afh[4][4], afl[4][4], bfh[4][2], bfl[4][2];
            #pragma unroll
            for (int mt = 0; mt < 4; ++mt) {
                const int r = wm * 64 + mt * 16 + a_row;
                ldm_x4(afh[mt][0], afh[mt][1], afh[mt][2], afh[mt][3], smem_u32(&Ahi[slab][r][a_col]));
                ldm_x4(afl[mt][0], afl[mt][1], afl[mt][2], afl[mt][3], smem_u32(&Alo[slab][r][a_col]));
            }
            #pragma unroll
            for (int nt = 0; nt < 4; ++nt) {
                const int c = wn * 32 + nt * 8;
                ldm_x2t(bfh[nt][0], bfh[nt][1], smem_u32(&Bhi[slab][lane & 15][c]));
                ldm_x2t(bfl[nt][0], bfl[nt][1], smem_u32(&Blo[slab][lane & 15][c]));
            }
            #pragma unroll
            for (int mt = 0; mt < 4; ++mt)
                #pragma unroll
                for (int nt = 0; nt < 4; ++nt) {
                    mma16816(acc[mt][nt], afh[mt], bfh[nt]);
                    mma16816(acc[mt][nt], afh[mt], bfl[nt]);
                    mma16816(acc[mt][nt], afl[mt], bfh[nt]);
                }
        }
        __syncthreads();
        if (kt + 1 < KT) {
            store_tile();
            __syncthreads();
        }
    }

    // epilogue
    #pragma unroll
    for (int mt = 0; mt < 4; ++mt) {
        const int r = m0 + wm * 64 + mt * 16 + (lane >> 2);
        #pragma unroll
        for (int nt = 0; nt < 4; ++nt) {
            const int c = n0 + wn * 32 + nt * 8 + (lane & 3) * 2;
            float v0 = acc[mt][nt][0], v1 = acc[mt][nt][1];
            float v2 = acc[mt][nt][2], v3 = acc[mt][nt][3];
            if (BIAS) { v0 += bias[c]; v1 += bias[c + 1]; v2 += bias[c]; v3 += bias[c + 1]; }
            if (RELU) { v0 = fmaxf(v0, 0.f); v1 = fmaxf(v1, 0.f); v2 = fmaxf(v2, 0.f); v3 = fmaxf(v3, 0.f); }
            *reinterpret_cast<float2*>(C + (size_t)r * N + c)       = make_float2(v0, v1);
            *reinterpret_cast<float2*>(C + (size_t)(r + 8) * N + c) = make_float2(v2, v3);
        }
    }
}

// =====================================================================
// Fused QKV GEMM (bf16x3): X[2048,1024] @ virtual Wqkv[1024,3072]
// =====================================================================
__global__ void __launch_bounds__(256) qkv_bf16(
    const float* __restrict__ A,
    const float* __restrict__ wq, const float* __restrict__ wk,
    const float* __restrict__ wv)
{
    __shared__ __align__(16) __nv_bfloat16 Ahi[2][128][24];
    __shared__ __align__(16) __nv_bfloat16 Alo[2][128][24];
    __shared__ __align__(16) __nv_bfloat16 Bhi[2][16][136];
    __shared__ __align__(16) __nv_bfloat16 Blo[2][16][136];

    const int tid  = threadIdx.x;
    const int lane = tid & 31;
    const int wid  = tid >> 5;
    const int wm   = wid >> 2;
    const int wn   = wid & 3;
    const int m0   = blockIdx.y * 128;
    const int n0   = blockIdx.x * 128;
    const int K    = E;
    const int KT   = K >> 5;

    // per-thread B gather column (fixed across k)
    const int bidx  = tid & 31;            // col chunk within [0,128)
    const int ncol  = n0 + bidx * 4;
    const int which = ncol >> 10;
    const int head  = (ncol >> 6) & 15;
    const int d     = ncol & 63;
    const float* wsel  = (which == 0 ? wq : which == 1 ? wk : wv);
    const float* bbase = wsel + ((size_t)head * E) * Dh + d;   // + e*Dh

    float4 a_reg[4], b_reg[4];

    auto load_tile = [&](int kt) {
        const int k0 = kt << 5;
        #pragma unroll
        for (int i = 0; i < 4; ++i) {
            const int idx = tid + i * 256;
            const int row = idx >> 3, c4 = idx & 7;
            a_reg[i] = *reinterpret_cast<const float4*>(A + (size_t)(m0 + row) * K + k0 + c4 * 4);
        }
        #pragma unroll
        for (int i = 0; i < 4; ++i) {
            const int krow = (tid >> 5) + i * 8;   // 0..31, same col each i
            b_reg[i] = *reinterpret_cast<const float4*>(bbase + (size_t)(k0 + krow) * Dh);
        }
    };
    auto store_tile = [&]() {
        #pragma unroll
        for (int i = 0; i < 4; ++i) {
            const int idx = tid + i * 256;
            const int row = idx >> 3, c4 = idx & 7;
            const int slab = c4 >> 2, kk = (c4 & 3) * 4;
            uint2 hi, lo; split4(a_reg[i], hi, lo);
            *reinterpret_cast<uint2*>(&Ahi[slab][row][kk]) = hi;
            *reinterpret_cast<uint2*>(&Alo[slab][row][kk]) = lo;
        }
        #pragma unroll
        for (int i = 0; i < 4; ++i) {
            const int krow = (tid >> 5) + i * 8;
            const int slab = krow >> 4, kk = krow & 15;
            uint2 hi, lo; split4(b_reg[i], hi, lo);
            *reinterpret_cast<uint2*>(&Bhi[slab][kk][bidx * 4]) = hi;
            *reinterpret_cast<uint2*>(&Blo[slab][kk][bidx * 4]) = lo;
        }
    };

    float acc[4][4][4] = {};

    load_tile(0);
    store_tile();
    __syncthreads();

    const int a_row = (lane & 15);
    const int a_col = (lane >> 4) * 8;

    for (int kt = 0; kt < KT; ++kt) {
        if (kt + 1 < KT) load_tile(kt + 1);

        #pragma unroll
        for (int slab = 0; slab < 2; ++slab) {
            uint32_t afh[4][4], afl[4][4], bfh[4][2], bfl[4][2];
            #pragma unroll
            for (int mt = 0; mt < 4; ++mt) {
                const int r = wm * 64 + mt * 16 + a_row;
                ldm_x4(afh[mt][0], afh[mt][1], afh[mt][2], afh[mt][3], smem_u32(&Ahi[slab][r][a_col]));
                ldm_x4(afl[mt][0], afl[mt][1], afl[mt][2], afl[mt][3], smem_u32(&Alo[slab][r][a_col]));
            }
            #pragma unroll
            for (int nt = 0; nt < 4; ++nt) {
                const int c = wn * 32 + nt * 8;
                ldm_x2t(bfh[nt][0], bfh[nt][1], smem_u32(&Bhi[slab][lane & 15][c]));
                ldm_x2t(bfl[nt][0], bfl[nt][1], smem_u32(&Blo[slab][lane & 15][c]));
            }
            #pragma unroll
            for (int mt = 0; mt < 4; ++mt)
                #pragma unroll
                for (int nt = 0; nt < 4; ++nt) {
                    mma16816(acc[mt][nt], afh[mt], bfh[nt]);
                    mma16816(acc[mt][nt], afh[mt], bfl[nt]);
                    mma16816(acc[mt][nt], afl[mt], bfh[nt]);
                }
        }
        __syncthreads();
        if (kt + 1 < KT) {
            store_tile();
            __syncthreads();
        }
    }

    // scatter epilogue to g_Q / g_K / g_V
    #pragma unroll
    for (int mt = 0; mt < 4; ++mt) {
        const int m = m0 + wm * 64 + mt * 16 + (lane >> 2);
        #pragma unroll
        for (int nt = 0; nt < 4; ++nt) {
            const int nn = n0 + wn * 32 + nt * 8 + (lane & 3) * 2;
            const int w2 = nn >> 10;
            const int h2 = (nn >> 6) & 15;
            const int d2 = nn & 63;
            float* dst = (w2 == 0 ? g_Q : w2 == 1 ? g_K : g_V);
            *reinterpret_cast<float2*>(&dst[((size_t)h2 * T + m) * Dh + d2]) =
                make_float2(acc[mt][nt][0], acc[mt][nt][1]);
            *reinterpret_cast<float2*>(&dst[((size_t)h2 * T + m + 8) * Dh + d2]) =
                make_float2(acc[mt][nt][2], acc[mt][nt][3]);
        }
    }
}

// =====================================================================
// Tiled causal attention (unchanged from R2)
// =====================================================================
__global__ void __launch_bounds__(256) attn_kernel()
{
    __shared__ float4 Q4[32][17];
    __shared__ float4 K4[32][17];
    __shared__ float4 V4[32][17];
    __shared__ float  p_sh[8][4][32];

    const int tid  = threadIdx.x;
    const int w    = tid >> 5;
    const int lane = tid & 31;
    const int base = blockIdx.x * 32;
    const int h    = blockIdx.y;

    const float* Qh = g_Q + (size_t)h * T * Dh;
    const float* Kh = g_K + (size_t)h * T * Dh;
    const float* Vh = g_V + (size_t)h * T * Dh;
    const float* Vf = (const float*)V4;

    #pragma unroll
    for (int i = 0; i < 2; ++i) {
        const int idx = tid + i * 256;
        const int row = idx >> 4, c4 = idx & 15;
        Q4[row][c4] = *reinterpret_cast<const float4*>(Qh + (size_t)(base + row) * Dh + c4 * 4);
    }

    float m[4] = {-1e30f, -1e30f, -1e30f, -1e30f};
    float l[4] = {};
    float o0[4] = {}, o1[4] = {};

    for (int kb = 0; kb <= base; kb += 32) {
        __syncthreads();
        #pragma unroll
        for (int i = 0; i < 2; ++i) {
            const int idx = tid + i * 256;
            const int row = idx >> 4, c4 = idx & 15;
            K4[row][c4] = *reinterpret_cast<const float4*>(Kh + (size_t)(kb + row) * Dh + c4 * 4);
            V4[row][c4] = *reinterpret_cast<const float4*>(Vh + (size_t)(kb + row) * Dh + c4 * 4);
        }
        __syncthreads();

        float s0 = 0.f, s1 = 0.f, s2 = 0.f, s3 = 0.f;
        #pragma unroll
        for (int d4 = 0; d4 < 16; ++d4) {
            const float4 kv = K4[lane][d4];
            float4 q;
            q = Q4[w * 4 + 0][d4]; s0 += q.x*kv.x + q.y*kv.y + q.z*kv.z + q.w*kv.w;
            q = Q4[w * 4 + 1][d4]; s1 += q.x*kv.x + q.y*kv.y + q.z*kv.z + q.w*kv.w;
            q = Q4[w * 4 + 2][d4]; s2 += q.x*kv.x + q.y*kv.y + q.z*kv.z + q.w*kv.w;
            q = Q4[w * 4 + 3][d4]; s3 += q.x*kv.x + q.y*kv.y + q.z*kv.z + q.w*kv.w;
        }
        float sv[4] = {s0, s1, s2, s3};
        const int j = kb + lane;

        #pragma unroll
        for (int r = 0; r < 4; ++r) {
            const int qrow = base + w * 4 + r;
            const bool act = (j <= qrow);
            float s = act ? sv[r] * 0.125f : -1e30f;
            float mc = s;
            #pragma unroll
            for (int o = 16; o; o >>= 1) mc = fmaxf(mc, __shfl_xor_sync(0xffffffffu, mc, o));
            const float mnew = fmaxf(m[r], mc);
            const float p = act ? __expf(s - mnew) : 0.0f;
            float ps = p;
            #pragma unroll
            for (int o = 16; o; o >>= 1) ps += __shfl_xor_sync(0xffffffffu, ps, o);
            const float alpha = __expf(m[r] - mnew);
            l[r]  = l[r] * alpha + ps;
            o0[r] *= alpha;
            o1[r] *= alpha;
            m[r]  = mnew;
            p_sh[w][r][lane] = p;
        }
        __syncwarp();

        #pragma unroll 4
        for (int jj = 0; jj < 32; ++jj) {
            const float va = Vf[jj * 68 + lane];
            const float vb = Vf[jj * 68 + lane + 32];
            const float pa = p_sh[w][0][jj];
            const float pb = p_sh[w][1][jj];
            const float pc = p_sh[w][2][jj];
            const float pd = p_sh[w][3][jj];
            o0[0] += pa * va;  o1[0] += pa * vb;
            o0[1] += pb * va;  o1[1] += pb * vb;
            o0[2] += pc * va;  o1[2] += pc * vb;
            o0[3] += pd * va;  o1[3] += pd * vb;
        }
        __syncwarp();
    }

    #pragma unroll
    for (int r = 0; r < 4; ++r) {
        const int qrow = base + w * 4 + r;
        const float inv = 1.0f / l[r];
        g_concat[(size_t)qrow * E + h * Dh + lane]      = o0[r] * inv;
        g_concat[(size_t)qrow * E + h * Dh + lane + 32] = o1[r] * inv;
    }
}

// ---------------- residual + LayerNorm ----------------
__device__ __forceinline__ void ln_body(const float* __restrict__ a,
                                        const float* __restrict__ b,
                                        const float* __restrict__ gamma,
                                        const float* __restrict__ beta,
                                        float* __restrict__ out)
{
    const int row = blockIdx.x;
    const int tid = threadIdx.x;

    float v[4];
    float s = 0.0f, s2 = 0.0f;
    #pragma unroll
    for (int i = 0; i < 4; ++i) {
        const int e = tid + i * 256;
        const float val = a[(size_t)row * E + e] + b[(size_t)row * E + e];
        v[i] = val;
        s += val;
        s2 += val * val;
    }

    __shared__ float shs[32], shq[32];
    #pragma unroll
    for (int o = 16; o; o >>= 1) {
        s  += __shfl_xor_sync(0xffffffffu, s, o);
        s2 += __shfl_xor_sync(0xffffffffu, s2, o);
    }
    const int warp = tid >> 5, lane = tid & 31;
    if (lane == 0) { shs[warp] = s; shq[warp] = s2; }
    __syncthreads();
    if (tid < 32) {
        s  = (tid < 8) ? shs[tid] : 0.0f;
        s2 = (tid < 8) ? shq[tid] : 0.0f;
        #pragma unroll
        for (int o = 4; o; o >>= 1) {
            s  += __shfl_xor_sync(0xffffffffu, s, o);
            s2 += __shfl_xor_sync(0xffffffffu, s2, o);
        }
        if (tid == 0) { shs[0] = s; shq[0] = s2; }
    }
    __syncthreads();
    s = shs[0]; s2 = shq[0];

    const float mean = s * (1.0f / E);
    const float var  = s2 * (1.0f / E) - mean * mean;
    const float inv  = rsqrtf(var + EPS);
    const float g    = gamma[0];
    #pragma unroll
    for (int i = 0; i < 4; ++i) {
        const int e = tid + i * 256;
        out[(size_t)row * E + e] = g * (v[i] - mean) * inv + beta[e];
    }
}

__global__ void ln1_kernel(const float* __restrict__ x,
                           const float* __restrict__ gamma,
                           const float* __restrict__ beta)
{
    ln_body(x, g_attn, gamma, beta, g_h);
}

__global__ void ln2_kernel(const float* __restrict__ gamma,
                           const float* __restrict__ beta,
                           float* __restrict__ out)
{
    ln_body(g_h, g_ffn, gamma, beta, out);
}

// ---------------- launch ----------------
extern "C" void kernel_launch(void* const* d_in, const int* in_sizes, int n_in,
                              void* d_out, int out_size)
{
    const float* x      = (const float*)d_in[0];
    const float* wq     = (const float*)d_in[1];
    const float* wk     = (const float*)d_in[2];
    const float* wv     = (const float*)d_in[3];
    const float* pool_w = (const float*)d_in[4];
    const float* l1_w   = (const float*)d_in[5];
    const float* l1_b   = (const float*)d_in[6];
    const float* l2_w   = (const float*)d_in[7];
    const float* l2_b   = (const float*)d_in[8];
    const float* gamma  = (const float*)d_in[9];
    const float* beta   = (const float*)d_in[10];
    float* out = (float*)d_out;

    float* pC; cudaGetSymbolAddress((void**)&pC, g_concat);
    float* pA; cudaGetSymbolAddress((void**)&pA, g_attn);
    float* pH; cudaGetSymbolAddress((void**)&pH, g_h);
    float* pF; cudaGetSymbolAddress((void**)&pF, g_f);
    float* pN; cudaGetSymbolAddress((void**)&pN, g_ffn);

    qkv_bf16<<<dim3(3072 / 128, T / 128), 256>>>(x, wq, wk, wv);
    attn_kernel<<<dim3(T / 32, H), 256>>>();
    gemm_bf16<0, 0><<<dim3(E / 128, T / 128), 256>>>(pC, pool_w, nullptr, pA, E, E);
    ln1_kernel<<<T, 256>>>(x, gamma, beta);
    gemm_bf16<1, 1><<<dim3(F / 128, T / 128), 256>>>(pH, l1_w, l1_b, pF, F, E);
    gemm_bf16<1, 0><<<dim3(E / 128, T / 128), 256>>>(pF, l2_w, l2_b, pN, E, F);
    ln2_kernel<<<T, 256>>>(gamma, beta, out);
}

// round 4
// speedup vs baseline: 14.5726x; 1.5733x over previous
#include <cuda_runtime.h>
#include <cuda_bf16.h>
#include <cstdint>

#define T  2048
#define E  1024
#define H  16
#define Dh 64
#define F  4096
#define EPS 1e-5f

// ---------------- scratch ----------------
__device__ __nv_bfloat16 g_Qh[H * T * Dh];
__device__ __nv_bfloat16 g_Ql[H * T * Dh];
__device__ __nv_bfloat16 g_Kh[H * T * Dh];
__device__ __nv_bfloat16 g_Kl[H * T * Dh];
__device__ __nv_bfloat16 g_Vh[H * T * Dh];
__device__ __nv_bfloat16 g_Vl[H * T * Dh];
__device__ float g_concat[T * E];
__device__ float g_attn[T * E];
__device__ float g_h[T * E];
__device__ float g_f[T * F];
__device__ float g_ffn[T * E];

// ---------------- mma helpers ----------------
__device__ __forceinline__ uint32_t smem_u32(const void* p) {
    return (uint32_t)__cvta_generic_to_shared(p);
}
__device__ __forceinline__ void ldm_x4(uint32_t* r, uint32_t a) {
    asm volatile("ldmatrix.sync.aligned.m8n8.x4.shared.b16 {%0,%1,%2,%3},[%4];"
                 : "=r"(r[0]), "=r"(r[1]), "=r"(r[2]), "=r"(r[3]) : "r"(a));
}
__device__ __forceinline__ void ldm_x4t(uint32_t* r, uint32_t a) {
    asm volatile("ldmatrix.sync.aligned.m8n8.x4.trans.shared.b16 {%0,%1,%2,%3},[%4];"
                 : "=r"(r[0]), "=r"(r[1]), "=r"(r[2]), "=r"(r[3]) : "r"(a));
}
__device__ __forceinline__ void ldm_x2t(uint32_t& r0, uint32_t& r1, uint32_t a) {
    asm volatile("ldmatrix.sync.aligned.m8n8.x2.trans.shared.b16 {%0,%1},[%2];"
                 : "=r"(r0), "=r"(r1) : "r"(a));
}
__device__ __forceinline__ void mma16816(float* d, const uint32_t* a, const uint32_t* b) {
    asm volatile(
        "mma.sync.aligned.m16n8k16.row.col.f32.bf16.bf16.f32 "
        "{%0,%1,%2,%3},{%4,%5,%6,%7},{%8,%9},{%0,%1,%2,%3};"
        : "+f"(d[0]), "+f"(d[1]), "+f"(d[2]), "+f"(d[3])
        : "r"(a[0]), "r"(a[1]), "r"(a[2]), "r"(a[3]), "r"(b[0]), "r"(b[1]));
}
__device__ __forceinline__ uint32_t pack_b2(__nv_bfloat16 a, __nv_bfloat16 b) {
    __nv_bfloat162 t = __halves2bfloat162(a, b);
    return *reinterpret_cast<uint32_t*>(&t);
}
__device__ __forceinline__ void split4(float4 v, uint2& hi, uint2& lo) {
    float f[4] = {v.x, v.y, v.z, v.w};
    __nv_bfloat16 h[4], l[4];
    #pragma unroll
    for (int i = 0; i < 4; ++i) {
        h[i] = __float2bfloat16(f[i]);
        l[i] = __float2bfloat16(f[i] - __bfloat162float(h[i]));
    }
    hi.x = pack_b2(h[0], h[1]); hi.y = pack_b2(h[2], h[3]);
    lo.x = pack_b2(l[0], l[1]); lo.y = pack_b2(l[2], l[3]);
}
__device__ __forceinline__ void pack_hilo(float x, float y, uint32_t& hi, uint32_t& lo) {
    __nv_bfloat16 hx = __float2bfloat16(x), hy = __float2bfloat16(y);
    __nv_bfloat16 lx = __float2bfloat16(x - __bfloat162float(hx));
    __nv_bfloat16 ly = __float2bfloat16(y - __bfloat162float(hy));
    hi = pack_b2(hx, hy); lo = pack_b2(lx, ly);
}
__device__ __forceinline__ void cp16(void* dst, const void* src) {
    asm volatile("cp.async.cg.shared.global [%0],[%1],16;" :: "r"(smem_u32(dst)), "l"(src));
}
__device__ __forceinline__ void cp_commit_wait() {
    asm volatile("cp.async.commit_group;\ncp.async.wait_group 0;" ::: "memory");
}

// =====================================================================
// bf16x3 tensor-core GEMM (unchanged from R3)
// =====================================================================
template<int BIAS, int RELU>
__global__ void __launch_bounds__(256) gemm_bf16(
    const float* __restrict__ A, const float* __restrict__ B,
    const float* __restrict__ bias, float* __restrict__ C,
    int N, int K)
{
    __shared__ __align__(16) __nv_bfloat16 Ahi[2][128][24];
    __shared__ __align__(16) __nv_bfloat16 Alo[2][128][24];
    __shared__ __align__(16) __nv_bfloat16 Bhi[2][16][136];
    __shared__ __align__(16) __nv_bfloat16 Blo[2][16][136];

    const int tid  = threadIdx.x;
    const int lane = tid & 31;
    const int wid  = tid >> 5;
    const int wm   = wid >> 2;
    const int wn   = wid & 3;
    const int m0   = blockIdx.y * 128;
    const int n0   = blockIdx.x * 128;
    const int KT   = K >> 5;

    float4 a_reg[4], b_reg[4];

    auto load_tile = [&](int kt) {
        const int k0 = kt << 5;
        #pragma unroll
        for (int i = 0; i < 4; ++i) {
            const int idx = tid + i * 256;
            const int row = idx >> 3, c4 = idx & 7;
            a_reg[i] = *reinterpret_cast<const float4*>(A + (size_t)(m0 + row) * K + k0 + c4 * 4);
        }
        #pragma unroll
        for (int i = 0; i < 4; ++i) {
            const int idx = tid + i * 256;
            const int row = idx >> 5, c4 = idx & 31;
            b_reg[i] = *reinterpret_cast<const float4*>(B + (size_t)(k0 + row) * N + n0 + c4 * 4);
        }
    };
    auto store_tile = [&]() {
        #pragma unroll
        for (int i = 0; i < 4; ++i) {
            const int idx = tid + i * 256;
            const int row = idx >> 3, c4 = idx & 7;
            const int slab = c4 >> 2, kk = (c4 & 3) * 4;
            uint2 hi, lo; split4(a_reg[i], hi, lo);
            *reinterpret_cast<uint2*>(&Ahi[slab][row][kk]) = hi;
            *reinterpret_cast<uint2*>(&Alo[slab][row][kk]) = lo;
        }
        #pragma unroll
        for (int i = 0; i < 4; ++i) {
            const int idx = tid + i * 256;
            const int row = idx >> 5, c4 = idx & 31;
            const int slab = row >> 4, kk = row & 15;
            uint2 hi, lo; split4(b_reg[i], hi, lo);
            *reinterpret_cast<uint2*>(&Bhi[slab][kk][c4 * 4]) = hi;
            *reinterpret_cast<uint2*>(&Blo[slab][kk][c4 * 4]) = lo;
        }
    };

    float acc[4][4][4] = {};
    load_tile(0);
    store_tile();
    __syncthreads();

    const int a_row = (lane & 15);
    const int a_col = (lane >> 4) * 8;

    for (int kt = 0; kt < KT; ++kt) {
        if (kt + 1 < KT) load_tile(kt + 1);

        #pragma unroll
        for (int slab = 0; slab < 2; ++slab) {
            uint32_t afh[4][4], afl[4][4], bfh[4][2], bfl[4][2];
            #pragma unroll
            for (int mt = 0; mt < 4; ++mt) {
                const int r = wm * 64 + mt * 16 + a_row;
                ldm_x4(afh[mt], smem_u32(&Ahi[slab][r][a_col]));
                ldm_x4(afl[mt], smem_u32(&Alo[slab][r][a_col]));
            }
            #pragma unroll
            for (int nt = 0; nt < 4; ++nt) {
                const int c = wn * 32 + nt * 8;
                ldm_x2t(bfh[nt][0], bfh[nt][1], smem_u32(&Bhi[slab][lane & 15][c]));
                ldm_x2t(bfl[nt][0], bfl[nt][1], smem_u32(&Blo[slab][lane & 15][c]));
            }
            #pragma unroll
            for (int mt = 0; mt < 4; ++mt)
                #pragma unroll
                for (int nt = 0; nt < 4; ++nt) {
                    mma16816(acc[mt][nt], afh[mt], bfh[nt]);
                    mma16816(acc[mt][nt], afh[mt], bfl[nt]);
                    mma16816(acc[mt][nt], afl[mt], bfh[nt]);
                }
        }
        __syncthreads();
        if (kt + 1 < KT) {
            store_tile();
            __syncthreads();
        }
    }

    #pragma unroll
    for (int mt = 0; mt < 4; ++mt) {
        const int r = m0 + wm * 64 + mt * 16 + (lane >> 2);
        #pragma unroll
        for (int nt = 0; nt < 4; ++nt) {
            const int c = n0 + wn * 32 + nt * 8 + (lane & 3) * 2;
            float v0 = acc[mt][nt][0], v1 = acc[mt][nt][1];
            float v2 = acc[mt][nt][2], v3 = acc[mt][nt][3];
            if (BIAS) { v0 += bias[c]; v1 += bias[c + 1]; v2 += bias[c]; v3 += bias[c + 1]; }
            if (RELU) { v0 = fmaxf(v0, 0.f); v1 = fmaxf(v1, 0.f); v2 = fmaxf(v2, 0.f); v3 = fmaxf(v3, 0.f); }
            *reinterpret_cast<float2*>(C + (size_t)r * N + c)       = make_float2(v0, v1);
            *reinterpret_cast<float2*>(C + (size_t)(r + 8) * N + c) = make_float2(v2, v3);
        }
    }
}

// =====================================================================
// Fused QKV GEMM (bf16x3) — epilogue writes Q/K/V as bf16 hi/lo pairs.
// Q is pre-scaled by 1/sqrt(Dh)=0.125 (exact power of 2).
// =====================================================================
__global__ void __launch_bounds__(256) qkv_bf16(
    const float* __restrict__ A,
    const float* __restrict__ wq, const float* __restrict__ wk,
    const float* __restrict__ wv)
{
    __shared__ __align__(16) __nv_bfloat16 Ahi[2][128][24];
    __shared__ __align__(16) __nv_bfloat16 Alo[2][128][24];
    __shared__ __align__(16) __nv_bfloat16 Bhi[2][16][136];
    __shared__ __align__(16) __nv_bfloat16 Blo[2][16][136];

    const int tid  = threadIdx.x;
    const int lane = tid & 31;
    const int wid  = tid >> 5;
    const int wm   = wid >> 2;
    const int wn   = wid & 3;
    const int m0   = blockIdx.y * 128;
    const int n0   = blockIdx.x * 128;
    const int K    = E;
    const int KT   = K >> 5;

    const int bidx  = tid & 31;
    const int ncol  = n0 + bidx * 4;
    const int which = ncol >> 10;
    const int head  = (ncol >> 6) & 15;
    const int d     = ncol & 63;
    const float* wsel  = (which == 0 ? wq : which == 1 ? wk : wv);
    const float* bbase = wsel + ((size_t)head * E) * Dh + d;

    float4 a_reg[4], b_reg[4];

    auto load_tile = [&](int kt) {
        const int k0 = kt << 5;
        #pragma unroll
        for (int i = 0; i < 4; ++i) {
            const int idx = tid + i * 256;
            const int row = idx >> 3, c4 = idx & 7;
            a_reg[i] = *reinterpret_cast<const float4*>(A + (size_t)(m0 + row) * K + k0 + c4 * 4);
        }
        #pragma unroll
        for (int i = 0; i < 4; ++i) {
            const int krow = (tid >> 5) + i * 8;
            b_reg[i] = *reinterpret_cast<const float4*>(bbase + (size_t)(k0 + krow) * Dh);
        }
    };
    auto store_tile = [&]() {
        #pragma unroll
        for (int i = 0; i < 4; ++i) {
            const int idx = tid + i * 256;
            const int row = idx >> 3, c4 = idx & 7;
            const int slab = c4 >> 2, kk = (c4 & 3) * 4;
            uint2 hi, lo; split4(a_reg[i], hi, lo);
            *reinterpret_cast<uint2*>(&Ahi[slab][row][kk]) = hi;
            *reinterpret_cast<uint2*>(&Alo[slab][row][kk]) = lo;
        }
        #pragma unroll
        for (int i = 0; i < 4; ++i) {
            const int krow = (tid >> 5) + i * 8;
            const int slab = krow >> 4, kk = krow & 15;
            uint2 hi, lo; split4(b_reg[i], hi, lo);
            *reinterpret_cast<uint2*>(&Bhi[slab][kk][bidx * 4]) = hi;
            *reinterpret_cast<uint2*>(&Blo[slab][kk][bidx * 4]) = lo;
        }
    };

    float acc[4][4][4] = {};
    load_tile(0);
    store_tile();
    __syncthreads();

    const int a_row = (lane & 15);
    const int a_col = (lane >> 4) * 8;

    for (int kt = 0; kt < KT; ++kt) {
        if (kt + 1 < KT) load_tile(kt + 1);

        #pragma unroll
        for (int slab = 0; slab < 2; ++slab) {
            uint32_t afh[4][4], afl[4][4], bfh[4][2], bfl[4][2];
            #pragma unroll
            for (int mt = 0; mt < 4; ++mt) {
                const int r = wm * 64 + mt * 16 + a_row;
                ldm_x4(afh[mt], smem_u32(&Ahi[slab][r][a_col]));
                ldm_x4(afl[mt], smem_u32(&Alo[slab][r][a_col]));
            }
            #pragma unroll
            for (int nt = 0; nt < 4; ++nt) {
                const int c = wn * 32 + nt * 8;
                ldm_x2t(bfh[nt][0], bfh[nt][1], smem_u32(&Bhi[slab][lane & 15][c]));
                ldm_x2t(bfl[nt][0], bfl[nt][1], smem_u32(&Blo[slab][lane & 15][c]));
            }
            #pragma unroll
            for (int mt = 0; mt < 4; ++mt)
                #pragma unroll
                for (int nt = 0; nt < 4; ++nt) {
                    mma16816(acc[mt][nt], afh[mt], bfh[nt]);
                    mma16816(acc[mt][nt], afh[mt], bfl[nt]);
                    mma16816(acc[mt][nt], afl[mt], bfh[nt]);
                }
        }
        __syncthreads();
        if (kt + 1 < KT) {
            store_tile();
            __syncthreads();
        }
    }

    // epilogue: split into bf16 hi/lo, Q pre-scaled by 0.125
    #pragma unroll
    for (int mt = 0; mt < 4; ++mt) {
        const int m = m0 + wm * 64 + mt * 16 + (lane >> 2);
        #pragma unroll
        for (int nt = 0; nt < 4; ++nt) {
            const int nn = n0 + wn * 32 + nt * 8 + (lane & 3) * 2;
            const int w2 = nn >> 10;
            const int h2 = (nn >> 6) & 15;
            const int d2 = nn & 63;
            float v0 = acc[mt][nt][0], v1 = acc[mt][nt][1];
            float v2 = acc[mt][nt][2], v3 = acc[mt][nt][3];
            if (w2 == 0) { v0 *= 0.125f; v1 *= 0.125f; v2 *= 0.125f; v3 *= 0.125f; }
            __nv_bfloat16* dh = (w2 == 0 ? g_Qh : w2 == 1 ? g_Kh : g_Vh);
            __nv_bfloat16* dl = (w2 == 0 ? g_Ql : w2 == 1 ? g_Kl : g_Vl);
            const size_t o0 = ((size_t)h2 * T + m) * Dh + d2;
            const size_t o1 = ((size_t)h2 * T + m + 8) * Dh + d2;
            uint32_t hi, lo;
            pack_hilo(v0, v1, hi, lo);
            *reinterpret_cast<uint32_t*>(&dh[o0]) = hi;
            *reinterpret_cast<uint32_t*>(&dl[o0]) = lo;
            pack_hilo(v2, v3, hi, lo);
            *reinterpret_cast<uint32_t*>(&dh[o1]) = hi;
            *reinterpret_cast<uint32_t*>(&dl[o1]) = lo;
        }
    }
}

// =====================================================================
// Tensor-core flash attention: block = 4 warps, 64 q-rows of one head.
// S = QhKh + QhKl + QlKh ; P split hi/lo in regs; O += PhVh + PlVh + PhVl.
// =====================================================================
__global__ void __launch_bounds__(128) attn_tc()
{
    __shared__ __align__(16) __nv_bfloat16 Kh_s[64][72];
    __shared__ __align__(16) __nv_bfloat16 Kl_s[64][72];
    __shared__ __align__(16) __nv_bfloat16 Vh_s[64][72];
    __shared__ __align__(16) __nv_bfloat16 Vl_s[64][72];

    const int tid  = threadIdx.x;
    const int lane = tid & 31;
    const int wid  = tid >> 5;
    const int qb   = (int)(gridDim.x - 1 - blockIdx.x) * 64;  // longest first
    const int h    = blockIdx.y;
    const int mbase = qb + wid * 16;

    const __nv_bfloat16* Qh = g_Qh + (size_t)h * T * Dh;
    const __nv_bfloat16* Ql = g_Ql + (size_t)h * T * Dh;
    const __nv_bfloat16* Kh = g_Kh + (size_t)h * T * Dh;
    const __nv_bfloat16* Kl = g_Kl + (size_t)h * T * Dh;
    const __nv_bfloat16* Vh = g_Vh + (size_t)h * T * Dh;
    const __nv_bfloat16* Vl = g_Vl + (size_t)h * T * Dh;

    // ---- prologue: stage Q tile through K buffers, ldmatrix to regs
    #pragma unroll
    for (int i = 0; i < 4; ++i) {
        const int idx = tid + i * 128;
        const int r = idx >> 3, c8 = idx & 7;
        cp16(&Kh_s[r][c8 * 8], Qh + (size_t)(qb + r) * Dh + c8 * 8);
        cp16(&Kl_s[r][c8 * 8], Ql + (size_t)(qb + r) * Dh + c8 * 8);
    }
    cp_commit_wait();
    __syncthreads();

    uint32_t qfh[4][4], qfl[4][4];
    #pragma unroll
    for (int ks = 0; ks < 4; ++ks) {
        const int r = wid * 16 + (lane & 15);
        const int c = ks * 16 + (lane >> 4) * 8;
        ldm_x4(qfh[ks], smem_u32(&Kh_s[r][c]));
        ldm_x4(qfl[ks], smem_u32(&Kl_s[r][c]));
    }
    __syncthreads();

    float oacc[8][4] = {};
    float m0 = -1e30f, m1 = -1e30f, l0 = 0.f, l1 = 0.f;
    const int niter = qb / 64 + 1;

    for (int it = 0; it < niter; ++it) {
        const int kb = it * 64;

        #pragma unroll
        for (int i = 0; i < 4; ++i) {
            const int idx = tid + i * 128;
            const int r = idx >> 3, c8 = idx & 7;
            const size_t go = (size_t)(kb + r) * Dh + c8 * 8;
            cp16(&Kh_s[r][c8 * 8], Kh + go);
            cp16(&Kl_s[r][c8 * 8], Kl + go);
            cp16(&Vh_s[r][c8 * 8], Vh + go);
            cp16(&Vl_s[r][c8 * 8], Vl + go);
        }
        cp_commit_wait();
        __syncthreads();

        // ---- S = Q @ K^T (m16 x n64 per warp)
        float sacc[8][4] = {};
        #pragma unroll
        for (int ks = 0; ks < 4; ++ks) {
            #pragma unroll
            for (int jp = 0; jp < 4; ++jp) {
                uint32_t bh[4], bl[4];
                const int row = jp * 16 + (lane & 7) + ((lane >> 4) << 3);
                const int col = ks * 16 + (((lane >> 3) & 1) << 3);
                ldm_x4(bh, smem_u32(&Kh_s[row][col]));
                ldm_x4(bl, smem_u32(&Kl_s[row][col]));
                mma16816(sacc[2 * jp],     qfh[ks], bh);
                mma16816(sacc[2 * jp],     qfh[ks], bl);
                mma16816(sacc[2 * jp],     qfl[ks], bh);
                mma16816(sacc[2 * jp + 1], qfh[ks], bh + 2);
                mma16816(sacc[2 * jp + 1], qfh[ks], bl + 2);
                mma16816(sacc[2 * jp + 1], qfl[ks], bh + 2);
            }
        }

        // ---- causal mask (only tiles crossing the diagonal)
        if (kb + 63 > mbase) {
            const int row0 = mbase + (lane >> 2);
            const int row1 = row0 + 8;
            const int cb   = kb + ((lane & 3) << 1);
            #pragma unroll
            for (int nt = 0; nt < 8; ++nt) {
                const int c = cb + nt * 8;
                if (c     > row0) sacc[nt][0] = -1e30f;
                if (c + 1 > row0) sacc[nt][1] = -1e30f;
                if (c     > row1) sacc[nt][2] = -1e30f;
                if (c + 1 > row1) sacc[nt][3] = -1e30f;
            }
        }

        // ---- online softmax (rows r, r+8 per thread; quad-reduce)
        float t0 = -1e30f, t1 = -1e30f;
        #pragma unroll
        for (int nt = 0; nt < 8; ++nt) {
            t0 = fmaxf(t0, fmaxf(sacc[nt][0], sacc[nt][1]));
            t1 = fmaxf(t1, fmaxf(sacc[nt][2], sacc[nt][3]));
        }
        t0 = fmaxf(t0, __shfl_xor_sync(0xffffffffu, t0, 1));
        t0 = fmaxf(t0, __shfl_xor_sync(0xffffffffu, t0, 2));
        t1 = fmaxf(t1, __shfl_xor_sync(0xffffffffu, t1, 1));
        t1 = fmaxf(t1, __shfl_xor_sync(0xffffffffu, t1, 2));
        const float mn0 = fmaxf(m0, t0), mn1 = fmaxf(m1, t1);
        const float a0 = __expf(m0 - mn0), a1 = __expf(m1 - mn1);
        m0 = mn0; m1 = mn1;

        float sum0 = 0.f, sum1 = 0.f;
        #pragma unroll
        for (int nt = 0; nt < 8; ++nt) {
            sacc[nt][0] = __expf(sacc[nt][0] - mn0);
            sacc[nt][1] = __expf(sacc[nt][1] - mn0);
            sacc[nt][2] = __expf(sacc[nt][2] - mn1);
            sacc[nt][3] = __expf(sacc[nt][3] - mn1);
            sum0 += sacc[nt][0] + sacc[nt][1];
            sum1 += sacc[nt][2] + sacc[nt][3];
        }
        sum0 += __shfl_xor_sync(0xffffffffu, sum0, 1);
        sum0 += __shfl_xor_sync(0xffffffffu, sum0, 2);
        sum1 += __shfl_xor_sync(0xffffffffu, sum1, 1);
        sum1 += __shfl_xor_sync(0xffffffffu, sum1, 2);
        l0 = l0 * a0 + sum0;
        l1 = l1 * a1 + sum1;

        #pragma unroll
        for (int nt = 0; nt < 8; ++nt) {
            oacc[nt][0] *= a0; oacc[nt][1] *= a0;
            oacc[nt][2] *= a1; oacc[nt][3] *= a1;
        }

        // ---- pack P into A-fragments (hi/lo), reuse S-fragment layout
        uint32_t pfh[4][4], pfl[4][4];
        #pragma unroll
        for (int ks = 0; ks < 4; ++ks) {
            pack_hilo(sacc[2 * ks][0],     sacc[2 * ks][1],     pfh[ks][0], pfl[ks][0]);
            pack_hilo(sacc[2 * ks][2],     sacc[2 * ks][3],     pfh[ks][1], pfl[ks][1]);
            pack_hilo(sacc[2 * ks + 1][0], sacc[2 * ks + 1][1], pfh[ks][2], pfl[ks][2]);
            pack_hilo(sacc[2 * ks + 1][2], sacc[2 * ks + 1][3], pfh[ks][3], pfl[ks][3]);
        }

        // ---- O += P @ V
        #pragma unroll
        for (int ks = 0; ks < 4; ++ks) {
            #pragma unroll
            for (int jp = 0; jp < 4; ++jp) {
                uint32_t vh[4], vl[4];
                const int row = ks * 16 + (lane & 15);
                const int col = jp * 16 + ((lane >> 4) << 3);
                ldm_x4t(vh, smem_u32(&Vh_s[row][col]));
                ldm_x4t(vl, smem_u32(&Vl_s[row][col]));
                mma16816(oacc[2 * jp],     pfh[ks], vh);
                mma16816(oacc[2 * jp],     pfl[ks], vh);
                mma16816(oacc[2 * jp],     pfh[ks], vl);
                mma16816(oacc[2 * jp + 1], pfh[ks], vh + 2);
                mma16816(oacc[2 * jp + 1], pfl[ks], vh + 2);
                mma16816(oacc[2 * jp + 1], pfh[ks], vl + 2);
            }
        }
        __syncthreads();
    }

    // ---- epilogue: divide by l, write concat layout
    const float i0 = 1.0f / l0, i1 = 1.0f / l1;
    const int r0 = mbase + (lane >> 2);
    const int cb = h * Dh + ((lane & 3) << 1);
    #pragma unroll
    for (int nt = 0; nt < 8; ++nt) {
        const int c = cb + nt * 8;
        *reinterpret_cast<float2*>(&g_concat[(size_t)r0 * E + c]) =
            make_float2(oacc[nt][0] * i0, oacc[nt][1] * i0);
        *reinterpret_cast<float2*>(&g_concat[(size_t)(r0 + 8) * E + c]) =
            make_float2(oacc[nt][2] * i1, oacc[nt][3] * i1);
    }
}

// ---------------- residual + LayerNorm ----------------
__device__ __forceinline__ void ln_body(const float* __restrict__ a,
                                        const float* __restrict__ b,
                                        const float* __restrict__ gamma,
                                        const float* __restrict__ beta,
                                        float* __restrict__ out)
{
    const int row = blockIdx.x;
    const int tid = threadIdx.x;

    float v[4];
    float s = 0.0f, s2 = 0.0f;
    #pragma unroll
    for (int i = 0; i < 4; ++i) {
        const int e = tid + i * 256;
        const float val = a[(size_t)row * E + e] + b[(size_t)row * E + e];
        v[i] = val;
        s += val;
        s2 += val * val;
    }

    __shared__ float shs[32], shq[32];
    #pragma unroll
    for (int o = 16; o; o >>= 1) {
        s  += __shfl_xor_sync(0xffffffffu, s, o);
        s2 += __shfl_xor_sync(0xffffffffu, s2, o);
    }
    const int warp = tid >> 5, lane = tid & 31;
    if (lane == 0) { shs[warp] = s; shq[warp] = s2; }
    __syncthreads();
    if (tid < 32) {
        s  = (tid < 8) ? shs[tid] : 0.0f;
        s2 = (tid < 8) ? shq[tid] : 0.0f;
        #pragma unroll
        for (int o = 4; o; o >>= 1) {
            s  += __shfl_xor_sync(0xffffffffu, s, o);
            s2 += __shfl_xor_sync(0xffffffffu, s2, o);
        }
        if (tid == 0) { shs[0] = s; shq[0] = s2; }
    }
    __syncthreads();
    s = shs[0]; s2 = shq[0];

    const float mean = s * (1.0f / E);
    const float var  = s2 * (1.0f / E) - mean * mean;
    const float inv  = rsqrtf(var + EPS);
    const float g    = gamma[0];
    #pragma unroll
    for (int i = 0; i < 4; ++i) {
        const int e = tid + i * 256;
        out[(size_t)row * E + e] = g * (v[i] - mean) * inv + beta[e];
    }
}

__global__ void ln1_kernel(const float* __restrict__ x,
                           const float* __restrict__ gamma,
                           const float* __restrict__ beta)
{
    ln_body(x, g_attn, gamma, beta, g_h);
}

__global__ void ln2_kernel(const float* __restrict__ gamma,
                           const float* __restrict__ beta,
                           float* __restrict__ out)
{
    ln_body(g_h, g_ffn, gamma, beta, out);
}

// ---------------- launch ----------------
extern "C" void kernel_launch(void* const* d_in, const int* in_sizes, int n_in,
                              void* d_out, int out_size)
{
    const float* x      = (const float*)d_in[0];
    const float* wq     = (const float*)d_in[1];
    const float* wk     = (const float*)d_in[2];
    const float* wv     = (const float*)d_in[3];
    const float* pool_w = (const float*)d_in[4];
    const float* l1_w   = (const float*)d_in[5];
    const float* l1_b   = (const float*)d_in[6];
    const float* l2_w   = (const float*)d_in[7];
    const float* l2_b   = (const float*)d_in[8];
    const float* gamma  = (const float*)d_in[9];
    const float* beta   = (const float*)d_in[10];
    float* out = (float*)d_out;

    float* pC; cudaGetSymbolAddress((void**)&pC, g_concat);
    float* pA; cudaGetSymbolAddress((void**)&pA, g_attn);
    float* pH; cudaGetSymbolAddress((void**)&pH, g_h);
    float* pF; cudaGetSymbolAddress((void**)&pF, g_f);
    float* pN; cudaGetSymbolAddress((void**)&pN, g_ffn);

    qkv_bf16<<<dim3(3072 / 128, T / 128), 256>>>(x, wq, wk, wv);
    attn_tc<<<dim3(T / 64, H), 128>>>();
    gemm_bf16<0, 0><<<dim3(E / 128, T / 128), 256>>>(pC, pool_w, nullptr, pA, E, E);
    ln1_kernel<<<T, 256>>>(x, gamma, beta);
    gemm_bf16<1, 1><<<dim3(F / 128, T / 128), 256>>>(pH, l1_w, l1_b, pF, F, E);
    gemm_bf16<1, 0><<<dim3(E / 128, T / 128), 256>>>(pF, l2_w, l2_b, pN, E, F);
    ln2_kernel<<<T, 256>>>(gamma, beta, out);
}